// round 3
// baseline (speedup 1.0000x reference)
#include <cuda_runtime.h>
#include <cstdint>

#define D        128
#define MAXB     16384
#define MAXREL   256
#define G        8       // samples per batch
#define NTH      256
#define GRID     592
#define MAXNB    (MAXB / G + MAXREL)     // padded batch capacity

// ---- scratch (no allocation allowed) ----
__device__ int g_sorted[MAXB + MAXREL * G];   // padded, relation-sorted sample ids
__device__ int g_brel[MAXNB];                 // relation of each padded batch
__device__ int g_bstart[MAXNB];               // start index into g_sorted
__device__ int g_nb;                          // number of padded batches

// ============ prep: everything in one single-block kernel ============
__global__ void k_prep(const int* __restrict__ rel, int B, int nrel) {
    __shared__ int cnt[MAXREL];
    __shared__ int poff[MAXREL];   // padded start offset in g_sorted
    __shared__ int cur[MAXREL];
    __shared__ int nsz[MAXREL];
    __shared__ int bidx[MAXREL];   // first batch index of relation
    const int tid = threadIdx.x;

    for (int i = tid; i < nrel; i += blockDim.x) cnt[i] = 0;
    __syncthreads();
    for (int i = tid; i < B; i += blockDim.x) atomicAdd(&cnt[rel[i]], 1);
    __syncthreads();
    if (tid == 0) {
        int accp = 0, accb = 0;
        for (int r = 0; r < nrel; r++) {
            int c  = cnt[r];
            int nb = (c + G - 1) / G;
            nsz[r] = c; poff[r] = accp; cur[r] = accp; bidx[r] = accb;
            accp += nb * G; accb += nb;
        }
        g_nb = accb;
    }
    __syncthreads();
    for (int i = tid; i < B; i += blockDim.x) {
        int r = rel[i];
        int p = atomicAdd(&cur[r], 1);
        g_sorted[p] = i;        // bucket order nondeterministic, output deterministic
    }
    __syncthreads();
    // padding fill + batch descriptors (parallel over relations)
    for (int r = tid; r < nrel; r += blockDim.x) {
        int c = nsz[r];
        if (!c) continue;
        int nb    = (c + G - 1) / G;
        int off   = poff[r];
        int first = g_sorted[off];
        for (int j = c; j < nb * G; j++) g_sorted[off + j] = first;
        int b0 = bidx[r];
        for (int b = 0; b < nb; b++) {
            g_brel[b0 + b]   = r;
            g_bstart[b0 + b] = off + b * G;
        }
    }
}

// ============ cp.async helpers ============
__device__ __forceinline__ void cpa16(void* dst, const void* src) {
    uint32_t d32 = (uint32_t)__cvta_generic_to_shared(dst);
    asm volatile("cp.async.cg.shared.global [%0], [%1], 16;\n"
                 :: "r"(d32), "l"(src) : "memory");
}
__device__ __forceinline__ void cpa_commit() {
    asm volatile("cp.async.commit_group;\n" ::: "memory");
}
template <int N>
__device__ __forceinline__ void cpa_wait() {
    asm volatile("cp.async.wait_group %0;\n" :: "n"(N) : "memory");
}

// ============ main compute ============
// 592 blocks, 256 threads. Block i handles padded batches [i*NB/592,(i+1)*NB/592),
// split into runs of equal relation; R staged once per run (swizzled smem).
// Thread (lane,w): wsub=w&3, d=lane+32*wsub, g0=(w>>2)*4.
extern "C" __global__ void __launch_bounds__(NTH, 2)
k_compute(const int*   __restrict__ heads,
          const int*   __restrict__ tails,
          const int*   __restrict__ nheads,
          const int*   __restrict__ ntails,
          const float* __restrict__ ent,
          const float* __restrict__ relm,
          float*       __restrict__ out,
          int B)
{
    extern __shared__ float sm[];
    float* Rs   = sm;                         // D*D swizzled
    float* Vb   = Rs + D * D;                 // [2 buf][4 vec][G][D]
    float* sc   = Vb + 2 * 4 * G * D;         // [2][G]
    int*   sidx = (int*)(sc + 2 * G);         // [2 buf][G]

    const int NB = g_nb;
    const int b0 = (int)((long long)blockIdx.x       * NB / GRID);
    const int b1 = (int)((long long)(blockIdx.x + 1) * NB / GRID);
    if (b0 >= b1) return;

    const int tid  = threadIdx.x;
    const int lane = tid & 31;
    const int w    = tid >> 5;
    const int wsub = w & 3;
    const int d    = lane + 32 * wsub;
    const int g0   = (w >> 2) * 4;

    if (tid < 2 * G) sc[tid] = 0.0f;

    int brun = b0;
    while (brun < b1) {
        const int rel = g_brel[brun];
        int rend = brun + 1;
        while (rend < b1 && g_brel[rend] == rel) rend++;
        const int nb = rend - brun;

        cpa_wait<0>();
        __syncthreads();                      // prior run fully done; Rs reusable

        // ---- stage R[rel] (swizzled) ----
        const float* Rg = relm + (size_t)rel * D * D;
#pragma unroll
        for (int k = 0; k < 16; k++) {
            int idx4 = tid + k * NTH;         // 0..4095 float4s
            int rd = idx4 >> 5, e4 = idx4 & 31;
            int slot = e4 * 128 + (rd ^ e4);
            cpa16(Rs + 4 * slot, Rg + 4 * idx4);
        }

        // ---- gather one batch (4 cp.async / thread) ----
        auto gather = [&](int lb) {
            int buf = lb & 1;
            int bstart = g_bstart[brun + lb];
            if (tid < G) sidx[buf * G + tid] = g_sorted[bstart + tid];
#pragma unroll
            for (int k = 0; k < 4; k++) {
                int q    = tid + k * NTH;     // 0..1023
                int col  = q & 31;
                int slot = q >> 5;
                int v    = slot & 3;
                int g    = slot >> 2;
                int i    = g_sorted[bstart + g];
                const int* arr = (v == 0) ? heads : (v == 1) ? tails
                               : (v == 2) ? nheads : ntails;
                int row = arr[i];
                cpa16(Vb + ((size_t)(buf * 4 + v) * G + g) * D + col * 4,
                      ent + (size_t)row * D + col * 4);
            }
        };

        gather(0);
        cpa_commit();                         // group: R + batch0
        if (nb > 1) gather(1);
        cpa_commit();                         // group: batch1 (maybe empty)

        for (int b = 0; b < nb; b++) {
            const int buf = b & 1;
            if (b + 1 < nb) cpa_wait<1>(); else cpa_wait<0>();
            __syncthreads();                  // buffer b (and R) ready

            const float* Hv  = Vb + (size_t)(buf * 4 + 0) * G * D;
            const float* Tv  = Vb + (size_t)(buf * 4 + 1) * G * D;
            const float* NHv = Vb + (size_t)(buf * 4 + 2) * G * D;
            const float* NTv = Vb + (size_t)(buf * 4 + 3) * G * D;

            float a0 = 0.f, a1 = 0.f, a2 = 0.f, a3 = 0.f;
            float c0 = 0.f, c1 = 0.f, c2 = 0.f, c3 = 0.f;

#pragma unroll 4
            for (int e4 = 0; e4 < 32; e4++) {
                float4 r = *(const float4*)(Rs + 4 * (e4 * 128 + (d ^ e4)));
                float4 t;
                t = *(const float4*)(Tv + (size_t)(g0 + 0) * D + 4 * e4);
                a0 = fmaf(r.x, t.x, a0); a0 = fmaf(r.y, t.y, a0);
                a0 = fmaf(r.z, t.z, a0); a0 = fmaf(r.w, t.w, a0);
                t = *(const float4*)(Tv + (size_t)(g0 + 1) * D + 4 * e4);
                a1 = fmaf(r.x, t.x, a1); a1 = fmaf(r.y, t.y, a1);
                a1 = fmaf(r.z, t.z, a1); a1 = fmaf(r.w, t.w, a1);
                t = *(const float4*)(Tv + (size_t)(g0 + 2) * D + 4 * e4);
                a2 = fmaf(r.x, t.x, a2); a2 = fmaf(r.y, t.y, a2);
                a2 = fmaf(r.z, t.z, a2); a2 = fmaf(r.w, t.w, a2);
                t = *(const float4*)(Tv + (size_t)(g0 + 3) * D + 4 * e4);
                a3 = fmaf(r.x, t.x, a3); a3 = fmaf(r.y, t.y, a3);
                a3 = fmaf(r.z, t.z, a3); a3 = fmaf(r.w, t.w, a3);
                t = *(const float4*)(NTv + (size_t)(g0 + 0) * D + 4 * e4);
                c0 = fmaf(r.x, t.x, c0); c0 = fmaf(r.y, t.y, c0);
                c0 = fmaf(r.z, t.z, c0); c0 = fmaf(r.w, t.w, c0);
                t = *(const float4*)(NTv + (size_t)(g0 + 1) * D + 4 * e4);
                c1 = fmaf(r.x, t.x, c1); c1 = fmaf(r.y, t.y, c1);
                c1 = fmaf(r.z, t.z, c1); c1 = fmaf(r.w, t.w, c1);
                t = *(const float4*)(NTv + (size_t)(g0 + 2) * D + 4 * e4);
                c2 = fmaf(r.x, t.x, c2); c2 = fmaf(r.y, t.y, c2);
                c2 = fmaf(r.z, t.z, c2); c2 = fmaf(r.w, t.w, c2);
                t = *(const float4*)(NTv + (size_t)(g0 + 3) * D + 4 * e4);
                c3 = fmaf(r.x, t.x, c3); c3 = fmaf(r.y, t.y, c3);
                c3 = fmaf(r.z, t.z, c3); c3 = fmaf(r.w, t.w, c3);
            }

            // ---- epilogue: multiply by h/nh, reduce over d ----
            float p0 = Hv[(size_t)(g0 + 0) * D + d] * a0;
            float p1 = Hv[(size_t)(g0 + 1) * D + d] * a1;
            float p2 = Hv[(size_t)(g0 + 2) * D + d] * a2;
            float p3 = Hv[(size_t)(g0 + 3) * D + d] * a3;
            float q0 = NHv[(size_t)(g0 + 0) * D + d] * c0;
            float q1 = NHv[(size_t)(g0 + 1) * D + d] * c1;
            float q2 = NHv[(size_t)(g0 + 2) * D + d] * c2;
            float q3 = NHv[(size_t)(g0 + 3) * D + d] * c3;
#pragma unroll
            for (int o = 16; o; o >>= 1) {
                p0 += __shfl_xor_sync(0xffffffffu, p0, o);
                p1 += __shfl_xor_sync(0xffffffffu, p1, o);
                p2 += __shfl_xor_sync(0xffffffffu, p2, o);
                p3 += __shfl_xor_sync(0xffffffffu, p3, o);
                q0 += __shfl_xor_sync(0xffffffffu, q0, o);
                q1 += __shfl_xor_sync(0xffffffffu, q1, o);
                q2 += __shfl_xor_sync(0xffffffffu, q2, o);
                q3 += __shfl_xor_sync(0xffffffffu, q3, o);
            }
            if (lane == 0) {
                atomicAdd(&sc[g0 + 0], p0);  atomicAdd(&sc[G + g0 + 0], q0);
                atomicAdd(&sc[g0 + 1], p1);  atomicAdd(&sc[G + g0 + 1], q1);
                atomicAdd(&sc[g0 + 2], p2);  atomicAdd(&sc[G + g0 + 2], q2);
                atomicAdd(&sc[g0 + 3], p3);  atomicAdd(&sc[G + g0 + 3], q3);
            }
            __syncthreads();

            if (tid < G) {
                int i = sidx[buf * G + tid];
                out[i]     = sc[tid];
                out[B + i] = sc[G + tid];
                sc[tid] = 0.0f; sc[G + tid] = 0.0f;
            }
            __syncthreads();

            if (b + 2 < nb) gather(b + 2);
            cpa_commit();
        }
        brun = rend;
    }
}

// ============ launch ============
extern "C" void kernel_launch(void* const* d_in, const int* in_sizes, int n_in,
                              void* d_out, int out_size)
{
    const int*   heads  = (const int*)  d_in[0];
    const int*   tails  = (const int*)  d_in[1];
    const int*   nheads = (const int*)  d_in[2];
    const int*   ntails = (const int*)  d_in[3];
    const int*   rels   = (const int*)  d_in[4];
    const float* ent    = (const float*)d_in[5];
    const float* relm   = (const float*)d_in[6];
    float*       out    = (float*)      d_out;

    const int B    = in_sizes[0];
    const int nrel = in_sizes[6] / (D * D);

    k_prep<<<1, 1024>>>(rels, B, nrel);

    const size_t smem_bytes =
        (D * D + 2 * 4 * G * D + 2 * G) * sizeof(float) + 2 * G * sizeof(int);
    cudaFuncSetAttribute(k_compute, cudaFuncAttributeMaxDynamicSharedMemorySize,
                         (int)smem_bytes);
    k_compute<<<GRID, NTH, smem_bytes>>>(heads, tails, nheads, ntails,
                                         ent, relm, out, B);
}

// round 5
// speedup vs baseline: 2.6335x; 2.6335x over previous
#include <cuda_runtime.h>
#include <cuda_bf16.h>
#include <cstdint>

#define D    128
#define CAP  2048
#define NTH  256

// smem layout (bytes): bf16 tiles, 128 rows x 256B (swizzled)
#define OFF_RH   0
#define OFF_RL   32768
#define OFF_AH   65536
#define OFF_AL   98304
#define OFF_SIDX 131072
#define SMEM_BYTES (131072 + CAP * 4)

// ---------------- helpers ----------------
__device__ __forceinline__ uint32_t smem_u32(const void* p) {
    return (uint32_t)__cvta_generic_to_shared(p);
}
// swizzled byte offset within a [row][256B] tile: 16B chunk XOR by (row&7)
__device__ __forceinline__ int swz(int row, int kbyte) {
    return row * 256 + (kbyte ^ ((row & 7) << 4));
}
__device__ __forceinline__ uint32_t pkbf(__nv_bfloat16 a, __nv_bfloat16 b) {
    return (uint32_t)__bfloat16_as_ushort(a) | ((uint32_t)__bfloat16_as_ushort(b) << 16);
}
__device__ __forceinline__ void split4(float4 v, uint2& hi, uint2& lo) {
    __nv_bfloat16 hx = __float2bfloat16(v.x), hy = __float2bfloat16(v.y);
    __nv_bfloat16 hz = __float2bfloat16(v.z), hw = __float2bfloat16(v.w);
    __nv_bfloat16 lx = __float2bfloat16(v.x - __bfloat162float(hx));
    __nv_bfloat16 ly = __float2bfloat16(v.y - __bfloat162float(hy));
    __nv_bfloat16 lz = __float2bfloat16(v.z - __bfloat162float(hz));
    __nv_bfloat16 lw = __float2bfloat16(v.w - __bfloat162float(hw));
    hi.x = pkbf(hx, hy); hi.y = pkbf(hz, hw);
    lo.x = pkbf(lx, ly); lo.y = pkbf(lz, lw);
}
__device__ __forceinline__ void ldsm_x4(uint32_t& r0, uint32_t& r1,
                                        uint32_t& r2, uint32_t& r3, uint32_t a) {
    asm volatile("ldmatrix.sync.aligned.m8n8.x4.shared.b16 {%0,%1,%2,%3}, [%4];"
                 : "=r"(r0), "=r"(r1), "=r"(r2), "=r"(r3) : "r"(a));
}
__device__ __forceinline__ void ldsm_x2(uint32_t& r0, uint32_t& r1, uint32_t a) {
    asm volatile("ldmatrix.sync.aligned.m8n8.x2.shared.b16 {%0,%1}, [%2];"
                 : "=r"(r0), "=r"(r1) : "r"(a));
}
__device__ __forceinline__ void mma_bf16(float& c0, float& c1, float& c2, float& c3,
                                         uint32_t a0, uint32_t a1, uint32_t a2,
                                         uint32_t a3, uint32_t b0, uint32_t b1) {
    asm volatile(
        "mma.sync.aligned.m16n8k16.row.col.f32.bf16.bf16.f32 "
        "{%0,%1,%2,%3}, {%4,%5,%6,%7}, {%8,%9}, {%0,%1,%2,%3};"
        : "+f"(c0), "+f"(c1), "+f"(c2), "+f"(c3)
        : "r"(a0), "r"(a1), "r"(a2), "r"(a3), "r"(b0), "r"(b1));
}

// ---------------- main kernel: one CTA per relation ----------------
extern "C" __global__ void __launch_bounds__(NTH, 1)
k_rescal(const int*   __restrict__ heads,
         const int*   __restrict__ tails,
         const int*   __restrict__ nheads,
         const int*   __restrict__ ntails,
         const int*   __restrict__ rels,
         const float* __restrict__ ent,
         const float* __restrict__ relm,
         float*       __restrict__ out,
         int B)
{
    extern __shared__ char sm[];
    __shared__ int s_cnt;
    int* sidx = (int*)(sm + OFF_SIDX);

    const int tid  = threadIdx.x;
    const int wid  = tid >> 5;
    const int lane = tid & 31;
    const int r    = blockIdx.x;

    // ---- filter this relation's sample ids ----
    if (tid == 0) s_cnt = 0;
    __syncthreads();
    for (int i = tid; i < B; i += NTH)
        if (rels[i] == r) {
            int p = atomicAdd(&s_cnt, 1);
            if (p < CAP) sidx[p] = i;
        }
    __syncthreads();
    const int n = min(s_cnt, CAP);
    if (n == 0) return;

    // ---- stage R[r] -> bf16 hi/lo, swizzled [n_row][k] ----
    {
        const float4* Rg = (const float4*)(relm + (size_t)r * D * D);
#pragma unroll
        for (int k = 0; k < 16; k++) {
            int idx4 = tid + k * NTH;            // 0..4095
            float4 v = Rg[idx4];
            int row = idx4 >> 5;                 // output-dim d (B row)
            int e4  = idx4 & 31;
            uint2 hi, lo;
            split4(v, hi, lo);
            int bo = swz(row, e4 * 8);
            *(uint2*)(sm + OFF_RH + bo) = hi;
            *(uint2*)(sm + OFF_RL + bo) = lo;
        }
    }

    // per-thread ldmatrix address components (within warp's 16-row A block)
    const int s0     = wid * 16;
    const int a_row  = s0 + (lane & 7) + ((lane >> 3) & 1) * 8;
    const int a_koff = ((lane >> 4) & 1) * 16;   // bytes (+8 bf16)
    const uint32_t ah_base = smem_u32(sm + OFF_AH) + a_row * 256;
    const uint32_t al_base = smem_u32(sm + OFF_AL) + a_row * 256;
    const int a_xor  = (a_row & 7) << 4;
    const int b_lane = lane & 15;
    const int b_koff = ((b_lane >> 3) & 1) * 16;
    const int b_rsub = b_lane & 7;

    const int ntiles = (n + 127) >> 7;
    for (int t = 0; t < ntiles; t++) {
        const int tstart = t << 7;
        const int rows   = min(128, n - tstart);

        for (int side = 0; side < 2; side++) {
            const int* tarr = side ? ntails : tails;
            const int* harr = side ? nheads : heads;

            __syncthreads();                     // A buffers free (prev side done)
            // ---- stage A tile (rows x 128), zero-padded, hi/lo split ----
#pragma unroll
            for (int k = 0; k < 16; k++) {
                int idx4 = tid + k * NTH;
                int s = idx4 >> 5;
                int e4 = idx4 & 31;
                float4 v = make_float4(0.f, 0.f, 0.f, 0.f);
                if (s < rows) {
                    const float4* src = (const float4*)
                        (ent + (size_t)tarr[sidx[tstart + s]] * D);
                    v = src[e4];
                }
                uint2 hi, lo;
                split4(v, hi, lo);
                int bo = swz(s, e4 * 8);
                *(uint2*)(sm + OFF_AH + bo) = hi;
                *(uint2*)(sm + OFF_AL + bo) = lo;
            }
            __syncthreads();

            // ---- warp GEMM: 16 rows x 128 N x 128 K, 3-split bf16 ----
            float c[16][4];
#pragma unroll
            for (int nt = 0; nt < 16; nt++)
                c[nt][0] = c[nt][1] = c[nt][2] = c[nt][3] = 0.f;

#pragma unroll
            for (int ks = 0; ks < 8; ks++) {
                const int kb = ks * 32;          // byte offset of this k-step
                uint32_t th0, th1, th2, th3, tl0, tl1, tl2, tl3;
                ldsm_x4(th0, th1, th2, th3, ah_base + ((kb + a_koff) ^ a_xor));
                ldsm_x4(tl0, tl1, tl2, tl3, al_base + ((kb + a_koff) ^ a_xor));
#pragma unroll
                for (int nt = 0; nt < 16; nt++) {
                    const int nrow = nt * 8 + b_rsub;
                    const uint32_t boff = nrow * 256 + ((kb + b_koff) ^ ((nrow & 7) << 4));
                    uint32_t bh0, bh1, bl0, bl1;
                    ldsm_x2(bh0, bh1, smem_u32(sm + OFF_RH) + boff);
                    ldsm_x2(bl0, bl1, smem_u32(sm + OFF_RL) + boff);
                    mma_bf16(c[nt][0], c[nt][1], c[nt][2], c[nt][3],
                             th0, th1, th2, th3, bh0, bh1);
                    mma_bf16(c[nt][0], c[nt][1], c[nt][2], c[nt][3],
                             th0, th1, th2, th3, bl0, bl1);
                    mma_bf16(c[nt][0], c[nt][1], c[nt][2], c[nt][3],
                             tl0, tl1, tl2, tl3, bh0, bh1);
                }
            }

            // ---- epilogue: score = sum_n H[s][n] * Dmat[s][n] ----
            {
                const int r0 = lane >> 2;        // row within warp block
                const int r1 = r0 + 8;
                const int sg0 = tstart + s0 + r0;
                const int sg1 = tstart + s0 + r1;
                const bool v0 = (s0 + r0) < rows;
                const bool v1 = (s0 + r1) < rows;
                const int gi0 = sidx[v0 ? sg0 : tstart];
                const int gi1 = sidx[v1 ? sg1 : tstart];
                const float* hp0 = ent + (size_t)harr[gi0] * D;
                const float* hp1 = ent + (size_t)harr[gi1] * D;
                const int coff = 2 * (lane & 3);

                float acc0 = 0.f, acc1 = 0.f;
#pragma unroll
                for (int nt = 0; nt < 16; nt++) {
                    const int col = nt * 8 + coff;
                    float2 h0 = *(const float2*)(hp0 + col);
                    float2 h1 = *(const float2*)(hp1 + col);
                    acc0 = fmaf(c[nt][0], h0.x, acc0);
                    acc0 = fmaf(c[nt][1], h0.y, acc0);
                    acc1 = fmaf(c[nt][2], h1.x, acc1);
                    acc1 = fmaf(c[nt][3], h1.y, acc1);
                }
#pragma unroll
                for (int o = 1; o < 4; o <<= 1) {
                    acc0 += __shfl_xor_sync(0xffffffffu, acc0, o);
                    acc1 += __shfl_xor_sync(0xffffffffu, acc1, o);
                }
                if ((lane & 3) == 0) {
                    if (v0) out[(side ? B : 0) + gi0] = acc0;
                    if (v1) out[(side ? B : 0) + gi1] = acc1;
                }
            }
        }
    }
}

// ---------------- launch ----------------
extern "C" void kernel_launch(void* const* d_in, const int* in_sizes, int n_in,
                              void* d_out, int out_size)
{
    const int*   heads  = (const int*)  d_in[0];
    const int*   tails  = (const int*)  d_in[1];
    const int*   nheads = (const int*)  d_in[2];
    const int*   ntails = (const int*)  d_in[3];
    const int*   rels   = (const int*)  d_in[4];
    const float* ent    = (const float*)d_in[5];
    const float* relm   = (const float*)d_in[6];
    float*       out    = (float*)      d_out;

    const int B    = in_sizes[0];
    const int nrel = in_sizes[6] / (D * D);

    cudaFuncSetAttribute(k_rescal, cudaFuncAttributeMaxDynamicSharedMemorySize,
                         SMEM_BYTES);
    k_rescal<<<nrel, NTH, SMEM_BYTES>>>(heads, tails, nheads, ntails, rels,
                                        ent, relm, out, B);
}

// round 6
// speedup vs baseline: 3.4904x; 1.3254x over previous
#include <cuda_runtime.h>
#include <cuda_bf16.h>
#include <cstdint>

#define D    128
#define CAP  2048
#define NTH  512

// smem layout (bytes): bf16 tiles, 128 rows x 256B (swizzled)
#define OFF_RH   0
#define OFF_RL   32768
#define OFF_A0H  65536
#define OFF_A0L  98304
#define OFF_A1H  131072
#define OFF_A1L  163840
#define OFF_SIDX 196608
#define SMEM_BYTES (196608 + CAP * 4)

// ---------------- helpers ----------------
__device__ __forceinline__ uint32_t smem_u32(const void* p) {
    return (uint32_t)__cvta_generic_to_shared(p);
}
__device__ __forceinline__ int swz(int row, int kbyte) {
    return row * 256 + (kbyte ^ ((row & 7) << 4));
}
__device__ __forceinline__ uint32_t pkbf(__nv_bfloat16 a, __nv_bfloat16 b) {
    return (uint32_t)__bfloat16_as_ushort(a) | ((uint32_t)__bfloat16_as_ushort(b) << 16);
}
__device__ __forceinline__ void split4(float4 v, uint2& hi, uint2& lo) {
    __nv_bfloat16 hx = __float2bfloat16(v.x), hy = __float2bfloat16(v.y);
    __nv_bfloat16 hz = __float2bfloat16(v.z), hw = __float2bfloat16(v.w);
    __nv_bfloat16 lx = __float2bfloat16(v.x - __bfloat162float(hx));
    __nv_bfloat16 ly = __float2bfloat16(v.y - __bfloat162float(hy));
    __nv_bfloat16 lz = __float2bfloat16(v.z - __bfloat162float(hz));
    __nv_bfloat16 lw = __float2bfloat16(v.w - __bfloat162float(hw));
    hi.x = pkbf(hx, hy); hi.y = pkbf(hz, hw);
    lo.x = pkbf(lx, ly); lo.y = pkbf(lz, lw);
}
__device__ __forceinline__ void ldsm_x4(uint32_t& r0, uint32_t& r1,
                                        uint32_t& r2, uint32_t& r3, uint32_t a) {
    asm volatile("ldmatrix.sync.aligned.m8n8.x4.shared.b16 {%0,%1,%2,%3}, [%4];"
                 : "=r"(r0), "=r"(r1), "=r"(r2), "=r"(r3) : "r"(a));
}
__device__ __forceinline__ void mma_bf16(float& c0, float& c1, float& c2, float& c3,
                                         uint32_t a0, uint32_t a1, uint32_t a2,
                                         uint32_t a3, uint32_t b0, uint32_t b1) {
    asm volatile(
        "mma.sync.aligned.m16n8k16.row.col.f32.bf16.bf16.f32 "
        "{%0,%1,%2,%3}, {%4,%5,%6,%7}, {%8,%9}, {%0,%1,%2,%3};"
        : "+f"(c0), "+f"(c1), "+f"(c2), "+f"(c3)
        : "r"(a0), "r"(a1), "r"(a2), "r"(a3), "r"(b0), "r"(b1));
}

// ---------------- main kernel: one CTA per relation ----------------
extern "C" __global__ void __launch_bounds__(NTH, 1)
k_rescal(const int*   __restrict__ heads,
         const int*   __restrict__ tails,
         const int*   __restrict__ nheads,
         const int*   __restrict__ ntails,
         const int*   __restrict__ rels,
         const float* __restrict__ ent,
         const float* __restrict__ relm,
         float*       __restrict__ out,
         int B)
{
    extern __shared__ char sm[];
    __shared__ int s_cnt;
    int* sidx = (int*)(sm + OFF_SIDX);

    const int tid  = threadIdx.x;
    const int wid  = tid >> 5;
    const int lane = tid & 31;
    const int r    = blockIdx.x;

    // ---- filter this relation's sample ids (vectorized int4 scan) ----
    if (tid == 0) s_cnt = 0;
    __syncthreads();
    {
        const int4* r4 = (const int4*)rels;
        const int nq = B >> 2;
#pragma unroll 4
        for (int q = tid; q < nq; q += NTH) {
            int4 v = r4[q];
            int base = q << 2;
            if (v.x == r) { int p = atomicAdd(&s_cnt, 1); if (p < CAP) sidx[p] = base; }
            if (v.y == r) { int p = atomicAdd(&s_cnt, 1); if (p < CAP) sidx[p] = base + 1; }
            if (v.z == r) { int p = atomicAdd(&s_cnt, 1); if (p < CAP) sidx[p] = base + 2; }
            if (v.w == r) { int p = atomicAdd(&s_cnt, 1); if (p < CAP) sidx[p] = base + 3; }
        }
        for (int i = (nq << 2) + tid; i < B; i += NTH)
            if (rels[i] == r) { int p = atomicAdd(&s_cnt, 1); if (p < CAP) sidx[p] = i; }
    }
    __syncthreads();
    const int n = min(s_cnt, CAP);
    if (n == 0) return;

    // ---- stage R[r] -> bf16 hi/lo, swizzled [n_row][k] ----
    {
        const float4* Rg = (const float4*)(relm + (size_t)r * D * D);
#pragma unroll
        for (int k = 0; k < 8; k++) {
            int idx4 = tid + k * NTH;            // 0..4095
            float4 v = Rg[idx4];
            int row = idx4 >> 5;
            int e4  = idx4 & 31;
            uint2 hi, lo;
            split4(v, hi, lo);
            int bo = swz(row, e4 * 8);
            *(uint2*)(sm + OFF_RH + bo) = hi;
            *(uint2*)(sm + OFF_RL + bo) = lo;
        }
    }

    // per-warp role: warps 0-7 -> pos side, 8-15 -> neg side
    const int side = wid >> 3;
    const int ws   = wid & 7;
    const int s0   = ws * 16;
    const int* harr = side ? nheads : heads;

    const char* aH = sm + (side ? OFF_A1H : OFF_A0H);
    const char* aL = sm + (side ? OFF_A1L : OFF_A0L);
    const int a_row  = s0 + (lane & 7) + ((lane >> 3) & 1) * 8;
    const int a_koff = ((lane >> 4) & 1) * 16;
    const uint32_t ah_base = smem_u32(aH) + a_row * 256;
    const uint32_t al_base = smem_u32(aL) + a_row * 256;
    const int a_xor  = (a_row & 7) << 4;
    // B x4 addressing: mats {nt, nt+1}, lanes 16-31 -> second n-block
    const int b_rowc = ((lane >> 4) & 1) * 8 + (lane & 7);
    const int b_k    = ((lane >> 3) & 1) * 16;
    const uint32_t rh_u = smem_u32(sm + OFF_RH);
    const uint32_t rl_u = smem_u32(sm + OFF_RL);

    const int ntiles = (n + 127) >> 7;
    for (int t = 0; t < ntiles; t++) {
        const int tstart = t << 7;
        const int rows   = min(128, n - tstart);

        // ---- stage BOTH A tiles (pos & neg), zero-padded, hi/lo split ----
#pragma unroll
        for (int k = 0; k < 16; k++) {
            int idx  = tid + k * NTH;            // 0..8191
            int sd   = idx >> 12;                // 0: pos, 1: neg
            int rem  = idx & 4095;
            int s    = rem >> 5;
            int e4   = rem & 31;
            float4 v = make_float4(0.f, 0.f, 0.f, 0.f);
            if (s < rows) {
                const int* tarr = sd ? ntails : tails;
                const float4* src = (const float4*)
                    (ent + (size_t)tarr[sidx[tstart + s]] * D);
                v = src[e4];
            }
            uint2 hi, lo;
            split4(v, hi, lo);
            int bo = swz(s, e4 * 8);
            char* dh = sm + (sd ? OFF_A1H : OFF_A0H);
            char* dl = sm + (sd ? OFF_A1L : OFF_A0L);
            *(uint2*)(dh + bo) = hi;
            *(uint2*)(dl + bo) = lo;
        }
        __syncthreads();

        // ---- warp GEMM: 16 rows x 128 N x 128 K, 3-split bf16 ----
        float c[16][4];
#pragma unroll
        for (int nt = 0; nt < 16; nt++)
            c[nt][0] = c[nt][1] = c[nt][2] = c[nt][3] = 0.f;

#pragma unroll
        for (int ks = 0; ks < 8; ks++) {
            const int kb = ks * 32;
            uint32_t th0, th1, th2, th3, tl0, tl1, tl2, tl3;
            ldsm_x4(th0, th1, th2, th3, ah_base + ((kb + a_koff) ^ a_xor));
            ldsm_x4(tl0, tl1, tl2, tl3, al_base + ((kb + a_koff) ^ a_xor));
#pragma unroll
            for (int ntp = 0; ntp < 8; ntp++) {
                const int nrow = ntp * 16 + b_rowc;
                const uint32_t boff = nrow * 256 + ((kb + b_k) ^ ((nrow & 7) << 4));
                uint32_t bh0, bh1, bh2, bh3, bl0, bl1, bl2, bl3;
                ldsm_x4(bh0, bh1, bh2, bh3, rh_u + boff);
                ldsm_x4(bl0, bl1, bl2, bl3, rl_u + boff);
                const int nt = ntp * 2;
                mma_bf16(c[nt][0], c[nt][1], c[nt][2], c[nt][3],
                         th0, th1, th2, th3, bh0, bh1);
                mma_bf16(c[nt][0], c[nt][1], c[nt][2], c[nt][3],
                         th0, th1, th2, th3, bl0, bl1);
                mma_bf16(c[nt][0], c[nt][1], c[nt][2], c[nt][3],
                         tl0, tl1, tl2, tl3, bh0, bh1);
                mma_bf16(c[nt + 1][0], c[nt + 1][1], c[nt + 1][2], c[nt + 1][3],
                         th0, th1, th2, th3, bh2, bh3);
                mma_bf16(c[nt + 1][0], c[nt + 1][1], c[nt + 1][2], c[nt + 1][3],
                         th0, th1, th2, th3, bl2, bl3);
                mma_bf16(c[nt + 1][0], c[nt + 1][1], c[nt + 1][2], c[nt + 1][3],
                         tl0, tl1, tl2, tl3, bh2, bh3);
            }
        }

        // ---- epilogue: score = sum_n H[s][n] * Dmat[s][n] ----
        {
            const int rq  = lane >> 2;
            const bool v0 = (s0 + rq) < rows;
            const bool v1 = (s0 + rq + 8) < rows;
            const int gi0 = sidx[tstart + (v0 ? s0 + rq : 0)];
            const int gi1 = sidx[tstart + (v1 ? s0 + rq + 8 : 0)];
            const float* hp0 = ent + (size_t)harr[gi0] * D;
            const float* hp1 = ent + (size_t)harr[gi1] * D;
            const int coff = 2 * (lane & 3);

            float acc0 = 0.f, acc1 = 0.f;
#pragma unroll
            for (int nt = 0; nt < 16; nt++) {
                const int col = nt * 8 + coff;
                float2 h0 = *(const float2*)(hp0 + col);
                float2 h1 = *(const float2*)(hp1 + col);
                acc0 = fmaf(c[nt][0], h0.x, acc0);
                acc0 = fmaf(c[nt][1], h0.y, acc0);
                acc1 = fmaf(c[nt][2], h1.x, acc1);
                acc1 = fmaf(c[nt][3], h1.y, acc1);
            }
#pragma unroll
            for (int o = 1; o < 4; o <<= 1) {
                acc0 += __shfl_xor_sync(0xffffffffu, acc0, o);
                acc1 += __shfl_xor_sync(0xffffffffu, acc1, o);
            }
            if ((lane & 3) == 0) {
                if (v0) out[(side ? B : 0) + gi0] = acc0;
                if (v1) out[(side ? B : 0) + gi1] = acc1;
            }
        }
        __syncthreads();   // all warps done reading A/R before next tile restage
    }
}

// ---------------- launch ----------------
extern "C" void kernel_launch(void* const* d_in, const int* in_sizes, int n_in,
                              void* d_out, int out_size)
{
    const int*   heads  = (const int*)  d_in[0];
    const int*   tails  = (const int*)  d_in[1];
    const int*   nheads = (const int*)  d_in[2];
    const int*   ntails = (const int*)  d_in[3];
    const int*   rels   = (const int*)  d_in[4];
    const float* ent    = (const float*)d_in[5];
    const float* relm   = (const float*)d_in[6];
    float*       out    = (float*)      d_out;

    const int B    = in_sizes[0];
    const int nrel = in_sizes[6] / (D * D);

    cudaFuncSetAttribute(k_rescal, cudaFuncAttributeMaxDynamicSharedMemorySize,
                         SMEM_BYTES);
    k_rescal<<<nrel, NTH, SMEM_BYTES>>>(heads, tails, nheads, ntails, rels,
                                        ent, relm, out, B);
}